// round 10
// baseline (speedup 1.0000x reference)
#include <cuda_runtime.h>
#include <cuda_bf16.h>
#include <cstdint>

#define B_   16
#define N_   1024
#define TO_  20
#define JT_  327680
#define JPB  20
#define GB_  128

#if defined(__CUDA_ARCH_FEAT_SM103_ALL) || defined(__CUDA_ARCH_FEAT_SM100_ALL)
#define TC_PATH 1
#endif

typedef __nv_bfloat16 bf16;

// chunk-blocked pre-swizzled layouts: [kc][row][64 bf16], unit o stored at o^(row&7)
__device__ float g_qkvJ[(size_t)JT_*192];
__device__ __align__(256) bf16 g_xeh[(size_t)JT_*128], g_xel[(size_t)JT_*128];
__device__ __align__(256) bf16 g_atth[(size_t)JT_*64], g_attl[(size_t)JT_*64];
__device__ __align__(256) bf16 g_hch[(size_t)JT_*320], g_hcl[(size_t)JT_*320];
__device__ __align__(256) bf16 g_xth[(size_t)20480*1024], g_xtl[(size_t)20480*1024];
__device__ __align__(256) bf16 g_h01h[(size_t)JT_*128], g_h01l[(size_t)JT_*128];
__device__ __align__(256) bf16 g_Ah[4*1024*1024], g_Al[4*1024*1024];
__device__ __align__(256) bf16 g_wqkvh[24576], g_wqkvl[24576];
__device__ __align__(256) bf16 g_woh[4096],   g_wol[4096];
__device__ __align__(256) bf16 g_wgh[40960],  g_wgl[40960];
__device__ __align__(256) bf16 g_w3h[24576],  g_w3l[24576];
__device__ float g_bqkv[192], g_bo[64], g_bh[128], g_b3u[64];

__device__ __forceinline__ float bf2f(bf16 v) { return __bfloat162float(v); }
__device__ __forceinline__ uint32_t smem_u32(const void* p) {
    uint32_t a;
    asm("{ .reg .u64 t; cvta.to.shared.u64 t, %1; cvt.u32.u64 %0, t; }" : "=r"(a) : "l"(p));
    return a;
}
__device__ __forceinline__ int swe(int row, int k) { return ((((k >> 3) ^ (row & 7)) << 3) | (k & 7)); }

#ifdef TC_PATH
__device__ __forceinline__ uint32_t elect1() {
    uint32_t p;
    asm volatile("{\n\t.reg .pred p;\n\telect.sync _|p, 0xFFFFFFFF;\n\tselp.b32 %0, 1, 0, p;\n\t}" : "=r"(p));
    return p;
}
#define MBARRIER_INIT(addr, cnt) \
    asm volatile("mbarrier.init.shared.b64 [%0], %1;" :: "r"(addr), "r"(cnt) : "memory")
#define MBARRIER_INVAL(addr) \
    asm volatile("mbarrier.inval.shared.b64 [%0];" :: "r"(addr) : "memory")
#define MBAR_EXPECT(mbar, bytes) \
    asm volatile("mbarrier.arrive.expect_tx.shared.b64 _, [%0], %1;" \
        :: "r"((uint32_t)(mbar)), "r"((uint32_t)(bytes)) : "memory")
#define BULK_G2S(dst, src, bytes, mbar) \
    asm volatile("cp.async.bulk.shared::cluster.global.mbarrier::complete_tx::bytes [%0], [%1], %2, [%3];" \
        :: "r"((uint32_t)(dst)), "l"(src), "r"((uint32_t)(bytes)), "r"((uint32_t)(mbar)) : "memory")
#define MBAR_WAIT(mb, par) do { \
    uint32_t _m = (uint32_t)(mb), _p = (uint32_t)(par), _d; \
    asm volatile("{\n\t.reg .pred p;\n\t" \
        "mbarrier.try_wait.parity.acquire.cta.shared::cta.b64 p, [%1], %2;\n\t" \
        "selp.b32 %0, 1, 0, p;\n\t}" : "=r"(_d) : "r"(_m), "r"(_p) : "memory"); \
    if (!_d) { \
        asm volatile("{\n\t.reg .pred P1;\n\t" \
            "WL_%=:\n\t" \
            "mbarrier.try_wait.parity.acquire.cta.shared::cta.b64 P1, [%0], %1, 0x989680;\n\t" \
            "@P1 bra.uni WD_%=;\n\tbra.uni WL_%=;\n\tWD_%=:\n\t}" \
            :: "r"(_m), "r"(_p) : "memory"); \
    } \
} while(0)
#define TC_ALLOC(saddr, n) \
    asm volatile("tcgen05.alloc.cta_group::1.sync.aligned.shared::cta.b32 [%0], %1;" \
        :: "r"((uint32_t)(saddr)), "r"((uint32_t)(n)) : "memory")
#define TC_DEALLOC(tmem, n) \
    asm volatile("tcgen05.dealloc.cta_group::1.sync.aligned.b32 %0, %1;" :: "r"(tmem), "r"((uint32_t)(n)))
#define TC_RELINQ() asm volatile("tcgen05.relinquish_alloc_permit.cta_group::1.sync.aligned;")
#define TC_COMMIT(mbar) \
    asm volatile("tcgen05.commit.cta_group::1.mbarrier::arrive::one.shared::cluster.b64 [%0];" \
        :: "r"((uint32_t)(mbar)) : "memory")
#define TC_FENCE_AFTER() asm volatile("tcgen05.fence::after_thread_sync;" ::: "memory")
#define TC_WAIT_LD() asm volatile("tcgen05.wait::ld.sync.aligned;" ::: "memory")
#define TC_LD_X32(r, ta) \
    asm volatile("tcgen05.ld.sync.aligned.32x32b.x32.b32 " \
        "{%0, %1, %2, %3, %4, %5, %6, %7, %8, %9, %10, %11, %12, %13, %14, %15, " \
        " %16, %17, %18, %19, %20, %21, %22, %23, %24, %25, %26, %27, %28, %29, %30, %31}, [%32];" \
        : "=r"((r)[0]),  "=r"((r)[1]),  "=r"((r)[2]),  "=r"((r)[3]), \
          "=r"((r)[4]),  "=r"((r)[5]),  "=r"((r)[6]),  "=r"((r)[7]), \
          "=r"((r)[8]),  "=r"((r)[9]),  "=r"((r)[10]), "=r"((r)[11]), \
          "=r"((r)[12]), "=r"((r)[13]), "=r"((r)[14]), "=r"((r)[15]), \
          "=r"((r)[16]), "=r"((r)[17]), "=r"((r)[18]), "=r"((r)[19]), \
          "=r"((r)[20]), "=r"((r)[21]), "=r"((r)[22]), "=r"((r)[23]), \
          "=r"((r)[24]), "=r"((r)[25]), "=r"((r)[26]), "=r"((r)[27]), \
          "=r"((r)[28]), "=r"((r)[29]), "=r"((r)[30]), "=r"((r)[31]) \
        : "r"(ta))
__device__ __forceinline__ uint64_t make_desc(uint32_t addr) {
    return 0x4000404000010000ULL | (uint64_t)((addr >> 4) & 0x3FFF);
}
__device__ __forceinline__ void mma_bf(uint32_t d, uint64_t a, uint64_t b, uint32_t idesc, bool acc) {
    uint32_t en = acc ? 1u : 0u;
    asm volatile("{\n\t.reg .pred p;\n\tsetp.ne.u32 p, %5, 0;\n\t"
        "tcgen05.mma.cta_group::1.kind::f16 [%0], %1, %2, %3, {%4, %4, %4, %4}, p;\n\t}"
        :: "r"(d), "l"(a), "l"(b), "r"(idesc), "r"(0u), "r"(en) : "memory");
}
#define IDESC(n) (0x8000490u | (((n)/8) << 17))
#endif

// ---------------- weight split/pack (pre-swizzled) ----------------
__global__ void k_wsplit(const float* __restrict__ wq, const float* __restrict__ bq,
                         const float* __restrict__ wk, const float* __restrict__ bk,
                         const float* __restrict__ wv, const float* __restrict__ bv,
                         const float* __restrict__ wo, const float* __restrict__ bo,
                         const float* __restrict__ wg0, const float* __restrict__ bg0,
                         const float* __restrict__ wg1, const float* __restrict__ bg1,
                         const float* __restrict__ wadp, const float* __restrict__ badp,
                         const float* __restrict__ w0f) {
    int i = blockIdx.x * 256 + threadIdx.x;
    if (i < 24576) {
        int c = i / 12288, rem = i % 12288, r = rem / 64, k = rem & 63, col = c*64 + k;
        int s = r / 64, rr = r % 64;
        const float* W = (s == 0) ? wq : (s == 1) ? wk : wv;
        float v = (col < 96) ? W[rr*96 + col] : 0.f;
        bf16 h = __float2bfloat16(v);
        int si = (c*192 + r)*64 + swe(r, k);
        g_wqkvh[si] = h; g_wqkvl[si] = __float2bfloat16(v - bf2f(h));
    } else if (i < 28672) {
        int j = i - 24576;
        int n = j >> 6, k = j & 63;
        float v = wo[j];
        bf16 h = __float2bfloat16(v);
        int si = (n << 6) + swe(n, k);
        g_woh[si] = h; g_wol[si] = __float2bfloat16(v - bf2f(h));
    } else if (i < 69632) {
        int j = i - 28672;
        int c = j / 8192, rem = j % 8192, r = rem / 64, k = rem & 63, col = c*64 + k;
        float v;
        if (r < 64) v = (col < 192) ? wg0[r*192 + col] : 0.f;
        else {
            int rr = r - 64;
            if (col < 64) v = wg1[rr*192 + col];
            else if (col >= 192) v = wg1[rr*192 + col - 128];
            else v = 0.f;
        }
        bf16 h = __float2bfloat16(v);
        int si = (c*128 + r)*64 + swe(r, k);
        g_wgh[si] = h; g_wgl[si] = __float2bfloat16(v - bf2f(h));
    } else if (i < 94208) {
        int j = i - 69632;
        int c = j / 12288, rem = j % 12288, r = rem / 64, k = rem & 63, col = c*64 + k;
        float v;
        if (r < 64)       v = wadp[r*128 + col];
        else if (r < 128) v = (col < 64) ? w0f[(r-64)*64 + col] : 0.f;
        else              v = (col >= 64) ? w0f[(r-128)*64 + col - 64] : 0.f;
        bf16 h = __float2bfloat16(v);
        int si = (c*192 + r)*64 + swe(r, k);
        g_w3h[si] = h; g_w3l[si] = __float2bfloat16(v - bf2f(h));
    } else if (i < 94656) {
        int j = i - 94208;
        if (j < 192)      g_bqkv[j] = (j < 64) ? bq[j] : (j < 128) ? bk[j-64] : bv[j-128];
        else if (j < 256) g_bo[j-192] = bo[j-192];
        else if (j < 384) { int j2 = j-256; g_bh[j2] = (j2 < 64) ? bg0[j2] : bg1[j2-64]; }
        else              g_b3u[j-384] = badp[j-384];
    }
}

// ---------------- split graph matrices into [z][16][1024][64] pre-swizzled ----------------
__global__ void k_split_A(const float* __restrict__ A0, const float* __restrict__ A1,
                          const float* __restrict__ A2, const float* __restrict__ A3) {
    int u = blockIdx.x * 256 + threadIdx.x;
    int z = u >> 17, rem = u & 131071;
    int m = rem >> 7, uo = rem & 127;
    int kc = uo >> 3, o = uo & 7;
    const float* A = (z == 0) ? A0 : (z == 1) ? A1 : (z == 2) ? A2 : A3;
    const float* src = A + (size_t)m*1024 + uo*8;
    bf16 th[8], tl[8];
#pragma unroll
    for (int e = 0; e < 8; e++) {
        float v = src[e];
        bf16 h = __float2bfloat16(v);
        th[e] = h; tl[e] = __float2bfloat16(v - bf2f(h));
    }
    size_t dst = (((size_t)(z*16 + kc)*1024 + m) << 6) + ((o ^ (m & 7)) << 3);
    *(uint4*)(g_Ah + dst) = *(uint4*)th;
    *(uint4*)(g_Al + dst) = *(uint4*)tl;
}

// ---------------- fused dilated conv + tem slice -> xe [2][JT][64] ----------------
__global__ __launch_bounds__(256) void k_xe(const float* __restrict__ x,
                                            const float* __restrict__ tem,
                                            const float* __restrict__ w,
                                            const float* __restrict__ bias) {
    __shared__ float pool[9376];
    float* xs = pool;
    float* ws = pool + 3072;
    float* bs = pool + 9312;
    int tid = threadIdx.x;
    int b = blockIdx.x >> 8, n0 = (blockIdx.x & 255) * 4;
    for (int i = tid; i < 64*96; i += 256) { int o = i / 96, kk = i % 96; ws[kk*65 + o] = w[i]; }
    if (tid < 64) bs[tid] = bias[tid];
    for (int i = tid; i < 3072; i += 256) {
        int nn = i / 768, r = i % 768, ci = r / 24, tt = r % 24;
        xs[(nn*32 + ci)*24 + tt] = x[((size_t)(b*32 + ci)*1024 + n0 + nn)*24 + tt];
    }
    __syncthreads();
    int co = tid & 63, nn = tid >> 6;
    float acc[20];
#pragma unroll
    for (int t = 0; t < 20; t++) acc[t] = bs[co];
    for (int ci = 0; ci < 32; ci++) {
        float w0 = ws[(ci*3+0)*65 + co], w1 = ws[(ci*3+1)*65 + co], w2 = ws[(ci*3+2)*65 + co];
        const float* xr = &xs[(nn*32 + ci)*24];
#pragma unroll
        for (int t = 0; t < 20; t++) acc[t] += w0*xr[t] + w1*xr[t+2] + w2*xr[t+4];
    }
    __syncthreads();
    float* sxe = pool;
#pragma unroll
    for (int t = 0; t < 20; t++) sxe[(nn*20 + t)*96 + co] = fmaxf(acc[t], 0.f);
    for (int i = tid; i < 2560; i += 256) {
        int nn2 = i / 640, r = i % 640, ci = r / 20, t = r % 20;
        sxe[(nn2*20 + t)*96 + 64 + ci] = tem[((size_t)(b*32 + ci)*1024 + n0 + nn2)*24 + 4 + t];
    }
    __syncthreads();
    for (int idx = tid; idx < 2560; idx += 256) {
        int half = idx >= 1280;
        int e = half ? idx - 1280 : idx;
        int rr = e >> 4, uo = e & 15;
        int kc = uo >> 3, o = uo & 7;
        int nn2 = rr / 20, t = rr % 20;
        size_t J = (size_t)((b*1024 + n0 + nn2)*20 + t);
        const float* srow = &sxe[rr*96];
        bf16 tmp[8];
#pragma unroll
        for (int u = 0; u < 8; u++) {
            int c = uo*8 + u;
            float vv = (c < 96) ? srow[c] : 0.f;
            bf16 hv = __float2bfloat16(vv);
            tmp[u] = half ? __float2bfloat16(vv - bf2f(hv)) : hv;
        }
        size_t dst = (((size_t)kc*JT_ + J) << 6) + ((o ^ (J & 7)) << 3);
        *(uint4*)((half ? g_xel : g_xeh) + dst) = *(uint4*)tmp;
    }
}

// ---------------- persistent multi-tile tensor-core GEMM ----------------
struct GemmArgs {
    const bf16 *ah, *al;      // [K/64][JT][64] pre-swizzled
    const bf16 *wh, *wl;      // [K/64][N][64] pre-swizzled
    const float* bias;
    float* outf;              // MODE 0
    bf16 *oh, *ol;            // MODE 1/2: [Nout/64][JT][64]
    float* outfin;            // MODE 3
};

template<int K_, int NN, int MODE>
__global__ __launch_bounds__(256) void k_gemm(GemmArgs p) {
    constexpr int NCH = K_ / 64;
    constexpr int WB  = NN * 128;
    constexpr bool WRES = (K_ <= 128);            // weights SMEM-resident
    constexpr int WRB  = WRES ? NCH*2*WB : 0;
    constexpr int STG_ = WRES ? 32768 : 32768 + 2*WB;
    constexpr int GT  = JPB * NCH;
    extern __shared__ char smem[];
    int tid = threadIdx.x, wid = tid >> 5, lane = tid & 31;
    size_t J0 = (size_t)blockIdx.x * (JPB*128);
    float* Dt = (float*)(smem + 1024 + WRB + 2*STG_);

#ifdef TC_PATH
    uint32_t sb = smem_u32(smem);
    if (wid == 0) TC_ALLOC(sb, 512);
    if (tid == 0) {
        MBARRIER_INIT(sb+8, 1);  MBARRIER_INIT(sb+16, 1);   // full[0], full[1]
        MBARRIER_INIT(sb+24, 1); MBARRIER_INIT(sb+32, 1);   // mma[0],  mma[1]
        MBARRIER_INIT(sb+40, 1);                            // weights
    }
    __syncthreads();
    uint32_t tmem;
    asm volatile("ld.shared.b32 %0, [%1];" : "=r"(tmem) : "r"(sb));
    uint32_t wbase = sb + 1024;
    uint32_t abase = sb + 1024 + WRB;

    auto load_stage = [&](int g, uint32_t st) {
        int tile = g / NCH, c = g % NCH;
        uint32_t mb = sb + 8 + 8*(g & 1);
        MBAR_EXPECT(mb, STG_);
        const bf16* as = p.ah + (((size_t)c*JT_ + J0 + tile*128) << 6);
        const bf16* ls = p.al + (((size_t)c*JT_ + J0 + tile*128) << 6);
        BULK_G2S(st,          as, 16384, mb);
        BULK_G2S(st + 16384,  ls, 16384, mb);
        if (!WRES) {
            BULK_G2S(st + 32768,      p.wh + ((size_t)c*NN << 6), WB, mb);
            BULK_G2S(st + 32768 + WB, p.wl + ((size_t)c*NN << 6), WB, mb);
        }
    };

    int pending = -1;
    int sub = wid & 3, grp = wid >> 2;
    int m = sub*32 + lane;

    auto epilogue = [&](int tile) {
        TC_FENCE_AFTER();
        size_t J0t = J0 + (size_t)tile*128;
        uint32_t ta = tmem + (tile & 1)*256;
        if (MODE != 3) {
#pragma unroll
            for (int pp = 0; pp < NN/64; pp++) {
                uint32_t r[32];
                TC_LD_X32(r, ta + pp*64 + grp*32);
                TC_WAIT_LD();
#pragma unroll
                for (int c = 0; c < 32; c++) Dt[m*72 + grp*32 + c] = __uint_as_float(r[c]);
                __syncthreads();
                if (MODE == 0) {
                    for (int idx = tid; idx < 2048; idx += 256) {
                        int rr = idx >> 4, o = idx & 15;
                        float4 v;
                        v.x = Dt[rr*72 + o*4 + 0] + p.bias[pp*64 + o*4 + 0];
                        v.y = Dt[rr*72 + o*4 + 1] + p.bias[pp*64 + o*4 + 1];
                        v.z = Dt[rr*72 + o*4 + 2] + p.bias[pp*64 + o*4 + 2];
                        v.w = Dt[rr*72 + o*4 + 3] + p.bias[pp*64 + o*4 + 3];
                        *(float4*)(p.outf + (J0t + rr)*192 + pp*64 + o*4) = v;
                    }
                } else {
                    for (int idx = tid; idx < 1024; idx += 256) {
                        int rr = idx >> 3, o = idx & 7;
                        size_t J = J0t + rr;
                        bf16 th[8], tl[8];
#pragma unroll
                        for (int u = 0; u < 8; u++) {
                            float v = fmaxf(Dt[rr*72 + o*8 + u] + p.bias[pp*64 + o*8 + u], 0.f);
                            bf16 hv = __float2bfloat16(v);
                            th[u] = hv;
                            tl[u] = __float2bfloat16(v - bf2f(hv));
                        }
                        size_t ob = (((size_t)pp*JT_ + J) << 6) + ((o ^ (J & 7)) << 3);
                        *(uint4*)(p.oh + ob) = *(uint4*)th;
                        *(uint4*)(p.ol + ob) = *(uint4*)tl;
                    }
                }
                __syncthreads();
            }
        } else {
            float* sfin = Dt;
            uint32_t r[128];
            if (grp == 0) {
                TC_LD_X32(r,      ta);
                TC_LD_X32(r + 32, ta + 32);
                TC_LD_X32(r + 64, ta + 64);
                TC_LD_X32(r + 96, ta + 96);
            } else {
                TC_LD_X32(r,      ta + 128);
                TC_LD_X32(r + 32, ta + 160);
            }
            TC_WAIT_LD();
            if (grp == 1)
                for (int c = 0; c < 64; c++) sfin[c*132 + m] = __uint_as_float(r[c]);
            __syncthreads();
            if (grp == 0) {
                float s0 = 0.f, s1 = 0.f;
#pragma unroll
                for (int c = 0; c < 64; c++) {
                    float u = __uint_as_float(r[c]) + p.bias[c];
                    s0 += u * __uint_as_float(r[64 + c]);
                    s1 += u * sfin[c*132 + m];
                }
                float mx = fmaxf(s0, s1);
                float e0 = __expf(s0 - mx), e1 = __expf(s1 - mx);
                float inv = 1.f / (e0 + e1);
                float a0 = e0*inv, a1 = e1*inv;
                for (int c = 0; c < 64; c++)
                    sfin[c*132 + m] = a0*__uint_as_float(r[64 + c]) + a1*sfin[c*132 + m];
            }
            __syncthreads();
            int b = (int)(J0t / 20480);
            int joff = (int)(J0t % 20480);
            for (int idx = tid; idx < 2048; idx += 256) {
                int c = idx >> 5, o = idx & 31;
                float4 v;
                v.x = sfin[c*132 + o*4 + 0];
                v.y = sfin[c*132 + o*4 + 1];
                v.z = sfin[c*132 + o*4 + 2];
                v.w = sfin[c*132 + o*4 + 3];
                *(float4*)(p.outfin + (size_t)(b*64 + c)*20480 + joff + o*4) = v;
            }
            __syncthreads();
        }
    };

    if (wid == 0) {
        if (elect1()) {
            if (WRES) {
                MBAR_EXPECT(sb+40, NCH*2*WB);
                for (int c = 0; c < NCH; c++) {
                    BULK_G2S(wbase + (c*2)*WB,   p.wh + ((size_t)c*NN << 6), WB, sb+40);
                    BULK_G2S(wbase + (c*2+1)*WB, p.wl + ((size_t)c*NN << 6), WB, sb+40);
                }
            }
            load_stage(0, abase);
        }
    }
    for (int g = 0; g < GT; g++) {
        int buf = g & 1;
        if (g >= 1) MBAR_WAIT(sb + 24 + 8*((g - 1) & 1), ((g - 1) >> 1) & 1);
        if (wid == 0) {
            if (elect1()) {
                if (g + 1 < GT) load_stage(g + 1, abase + (1 - buf)*STG_);
                if (WRES && g == 0) MBAR_WAIT(sb+40, 0);
                MBAR_WAIT(sb + 8 + 8*buf, (g >> 1) & 1);
                int c = g % NCH, tile = g / NCH;
                uint32_t s0 = abase + buf*STG_;
                uint64_t ah = make_desc(s0);
                uint64_t al = make_desc(s0 + 16384);
                uint64_t wh = WRES ? make_desc(wbase + (c*2)*WB)   : make_desc(s0 + 32768);
                uint64_t wl = WRES ? make_desc(wbase + (c*2+1)*WB) : make_desc(s0 + 32768 + WB);
                uint32_t d = tmem + (tile & 1)*256;
#pragma unroll
                for (int ks = 0; ks < 4; ks++) {
                    mma_bf(d, ah + 2*ks, wh + 2*ks, IDESC(NN), !(c == 0 && ks == 0));
                    mma_bf(d, ah + 2*ks, wl + 2*ks, IDESC(NN), true);
                    mma_bf(d, al + 2*ks, wh + 2*ks, IDESC(NN), true);
                }
                TC_COMMIT(sb + 24 + 8*buf);
            }
        }
        if (pending >= 0) { epilogue(pending); pending = -1; }
        if (g % NCH == NCH - 1) pending = g / NCH;
    }
    MBAR_WAIT(sb + 24 + 8*((GT - 1) & 1), ((GT - 1) >> 1) & 1);
    epilogue(pending);
    __syncthreads();
    if (tid == 0) {
        MBARRIER_INVAL(sb+8); MBARRIER_INVAL(sb+16);
        MBARRIER_INVAL(sb+24); MBARRIER_INVAL(sb+32); MBARRIER_INVAL(sb+40);
    }
    if (wid == 0) { TC_RELINQ(); TC_DEALLOC(tmem, 512); }
#else
    for (int tile = 0; tile < JPB; tile++) {
        for (int mm = tid; mm < 128; mm += 256) {
            size_t J = J0 + (size_t)tile*128 + mm;
            float res[MODE == 3 ? 192 : NN];
            for (int n = 0; n < (MODE == 3 ? 192 : NN); n++) {
                float acc = 0.f;
                for (int k = 0; k < K_; k++) {
                    size_t ai = (((size_t)(k >> 6)*JT_ + J) << 6) + swe((int)(J & 7), k & 63);
                    float av = bf2f(p.ah[ai]) + bf2f(p.al[ai]);
                    size_t wi = (((size_t)(k >> 6)*NN + n) << 6) + swe(n, k & 63);
                    acc += av * (bf2f(p.wh[wi]) + bf2f(p.wl[wi]));
                }
                res[n] = acc;
            }
            if (MODE == 0) {
                for (int n = 0; n < NN; n++) p.outf[J*192 + n] = res[n] + p.bias[n];
            } else if (MODE == 3) {
                float s0 = 0.f, s1 = 0.f;
                for (int c = 0; c < 64; c++) {
                    float u = res[c] + p.bias[c];
                    s0 += u*res[64+c]; s1 += u*res[128+c];
                }
                float mx = fmaxf(s0, s1);
                float e0 = __expf(s0-mx), e1 = __expf(s1-mx), inv = 1.f/(e0+e1);
                int b = (int)(J/20480), rr = (int)(J%20480);
                for (int c = 0; c < 64; c++)
                    p.outfin[(size_t)(b*64+c)*20480 + rr] = (e0*res[64+c]+e1*res[128+c])*inv;
            } else {
                for (int n = 0; n < NN; n++) {
                    float v = fmaxf(res[n] + p.bias[n], 0.f);
                    bf16 hv = __float2bfloat16(v);
                    size_t ob = (((size_t)(n >> 6)*JT_ + J) << 6) + swe((int)(J & 7), n & 63);
                    p.oh[ob] = hv;
                    p.ol[ob] = __float2bfloat16(v - bf2f(hv));
                }
            }
        }
    }
#endif
}

// ---------------- attention: block per (b,n), warp per head ----------------
__global__ __launch_bounds__(256) void k_attn() {
    __shared__ float sq[20*196];
    __shared__ float Ss[8][400];
    __shared__ bf16 soh[20*72], sol[20*72];
    int tid = threadIdx.x, wid = tid >> 5, lane = tid & 31;
    size_t Jb = (size_t)blockIdx.x * 20;

    for (int idx = tid; idx < 960; idx += 256) {
        int t = idx / 48, o = idx % 48;
        *(float4*)&sq[t*196 + o*4] = *(const float4*)(g_qkvJ + (Jb + t)*192 + o*4);
    }
    __syncthreads();
    int h = wid;
    float* S = Ss[h];
    const int hb = h*8;
    for (int idx = lane; idx < 400; idx += 32) {
        int t = idx / 20, s = idx % 20;
        if (s <= t) {
            float acc = 0.f;
#pragma unroll
            for (int d = 0; d < 8; d++) acc += sq[t*196 + hb + d] * sq[s*196 + 64 + hb + d];
            S[idx] = acc * 0.35355339059327373f;
        }
    }
    __syncwarp();
    if (lane < 20) {
        int t = lane;
        float mx = -1e30f;
        for (int s = 0; s <= t; s++) mx = fmaxf(mx, S[t*20 + s]);
        float sum = 0.f;
        for (int s = 0; s <= t; s++) { float e = __expf(S[t*20 + s] - mx); S[t*20 + s] = e; sum += e; }
        float inv = 1.f / sum;
        for (int s = 0; s <= t; s++) S[t*20 + s] *= inv;
    }
    __syncwarp();
    for (int idx = lane; idx < 160; idx += 32) {
        int d = idx / 20, t = idx % 20;
        float acc = 0.f;
        for (int s = 0; s <= t; s++) acc += S[t*20 + s] * sq[s*196 + 128 + hb + d];
        bf16 hv = __float2bfloat16(acc);
        soh[t*72 + hb + d] = hv;
        sol[t*72 + hb + d] = __float2bfloat16(acc - bf2f(hv));
    }
    __syncthreads();
    if (tid < 160) {
        int t = tid >> 3, o = tid & 7;
        size_t J = Jb + t;
        size_t ob = (J << 6) + ((o ^ (J & 7)) << 3);
        bf16 th[8], tl[8];
#pragma unroll
        for (int u = 0; u < 8; u++) { th[u] = soh[t*72 + o*8 + u]; tl[u] = sol[t*72 + o*8 + u]; }
        *(uint4*)(g_atth + ob) = *(uint4*)th;
        *(uint4*)(g_attl + ob) = *(uint4*)tl;
    }
}

// ---------------- transpose x2 (hc kc=0) -> xt[kc][(b,t,c)][64] pre-swizzled ----------------
__global__ __launch_bounds__(256) void k_xt() {
    __shared__ bf16 th[64][72], tl[64][72];
    int tid = threadIdx.x;
    int b = blockIdx.x, t = blockIdx.y, n0 = blockIdx.z * 64;
    for (int i = tid; i < 512; i += 256) {
        int r = i >> 3, o = i & 7;
        size_t J = ((size_t)(b*1024 + n0 + r)*20 + t);
        size_t src = (J << 6) + ((o ^ (J & 7)) << 3);
        *(uint4*)(&th[r][o*8]) = *(const uint4*)(g_hch + src);
        *(uint4*)(&tl[r][o*8]) = *(const uint4*)(g_hcl + src);
    }
    __syncthreads();
    for (int i = tid; i < 512; i += 256) {
        int c = i >> 3, n8 = i & 7;
        bf16 vh[8], vl[8];
#pragma unroll
        for (int u = 0; u < 8; u++) { vh[u] = th[n8*8 + u][c]; vl[u] = tl[n8*8 + u][c]; }
        int j = b*1280 + t*64 + c;
        size_t dst = (((size_t)blockIdx.z*20480 + j) << 6) + ((n8 ^ (j & 7)) << 3);
        *(uint4*)(g_xth + dst) = *(uint4*)vh;
        *(uint4*)(g_xtl + dst) = *(uint4*)vl;
    }
}

// ---------------- nconv (bulk-copy pipeline) ----------------
#define NSTG 98304
#define NSMEM (1024 + 2*NSTG)
__global__ __launch_bounds__(256) void k_nconv_tc() {
    extern __shared__ char smem[];
    int tid = threadIdx.x, wid = tid >> 5, lane = tid & 31;
    int j0 = blockIdx.x * 256, m0 = blockIdx.y * 128, z = blockIdx.z;
    float* Dt = (float*)(smem + 1024);

#ifdef TC_PATH
    uint32_t sb = smem_u32(smem);
    if (wid == 0) TC_ALLOC(sb, 256);
    if (tid == 0) {
        MBARRIER_INIT(sb+8, 1);  MBARRIER_INIT(sb+16, 1);
        MBARRIER_INIT(sb+24, 1); MBARRIER_INIT(sb+32, 1);
    }
    __syncthreads();
    uint32_t tmem;
    asm volatile("ld.shared.b32 %0, [%1];" : "=r"(tmem) : "r"(sb));
    uint32_t bufb = sb + 1024;

    auto load_stage = [&](int kc, uint32_t st) {
        uint32_t mb = sb + 8 + 8*(kc & 1);
        MBAR_EXPECT(mb, NSTG);
        BULK_G2S(st,         g_Ah + (((size_t)(z*16 + kc)*1024 + m0) << 6), 16384, mb);
        BULK_G2S(st + 16384, g_Al + (((size_t)(z*16 + kc)*1024 + m0) << 6), 16384, mb);
        BULK_G2S(st + 32768, g_xth + (((size_t)kc*20480 + j0) << 6), 32768, mb);
        BULK_G2S(st + 65536, g_xtl + (((size_t)kc*20480 + j0) << 6), 32768, mb);
    };

    if (wid == 0) { if (elect1()) { load_stage(0, bufb); } }
    for (int ch = 0; ch < 16; ch++) {
        int buf = ch & 1;
        if (ch >= 1) MBAR_WAIT(sb + 24 + 8*((ch - 1) & 1), ((ch - 1) >> 1) & 1);
        if (wid == 0) {
            if (elect1()) {
                if (ch + 1 < 16) load_stage(ch + 1, bufb + (1 - buf)*NSTG);
                MBAR_WAIT(sb + 8 + 8*buf, (ch >> 1) & 1);
                uint32_t s0 = bufb + buf*NSTG;
                uint64_t ah = make_desc(s0);
                uint64_t al = make_desc(s0 + 16384);
                uint64_t xh = make_desc(s0 + 32768);
                uint64_t xl = make_desc(s0 + 65536);
#pragma unroll
                for (int ks = 0; ks < 4; ks++) {
                    mma_bf(tmem, ah + 2*ks, xh + 2*ks, IDESC(256), !(ch == 0 && ks == 0));
                    mma_bf(tmem, ah + 2*ks, xl + 2*ks, IDESC(256), true);
                    mma_bf(tmem, al + 2*ks, xh + 2*ks, IDESC(256), true);
                }
                TC_COMMIT(sb + 24 + 8*buf);
            }
        }
    }
    MBAR_WAIT(sb + 24 + 8, 1);
    TC_FENCE_AFTER();
    __syncthreads();
    {
        int sub = wid & 3, hf = wid >> 2;
        int m = sub*32 + lane;
#pragma unroll
        for (int i = 0; i < 4; i++) {
            uint32_t r[32];
            int cb = hf*128 + i*32;
            TC_LD_X32(r, tmem + cb);
            TC_WAIT_LD();
#pragma unroll
            for (int c = 0; c < 32; c++) Dt[(cb + c)*129 + m] = __uint_as_float(r[c]);
        }
    }
    __syncthreads();
    if (tid == 0) { MBARRIER_INVAL(sb+8); MBARRIER_INVAL(sb+16); MBARRIER_INVAL(sb+24); MBARRIER_INVAL(sb+32); }
    if (wid == 0) { TC_RELINQ(); TC_DEALLOC(tmem, 256); }
    __syncthreads();
#else
    for (int idx = tid; idx < 128*256; idx += 256) {
        int mm = idx >> 8, jl = idx & 255;
        int gm = m0 + mm, gj = j0 + jl;
        float acc = 0.f;
        for (int k = 0; k < 1024; k++) {
            size_t ai = (((size_t)(z*16 + (k >> 6))*1024 + gm) << 6) + swe(gm & 7, k & 63);
            size_t xi = (((size_t)(k >> 6)*20480 + gj) << 6) + swe(gj & 7, k & 63);
            acc += (bf2f(g_Ah[ai]) + bf2f(g_Al[ai])) * (bf2f(g_xth[xi]) + bf2f(g_xtl[xi]));
        }
        Dt[jl*129 + mm] = acc;
    }
    __syncthreads();
#endif

    int b = j0 / 1280, t0 = (j0 % 1280) / 64;
    for (int idx = tid; idx < 4096; idx += 256) {
        int rn = idx >> 3, o = idx & 7;
        int w = rn >> 2, tq = rn & 3;
        size_t J = (size_t)(b*1024 + m0 + w)*20 + t0 + tq;
        size_t ob = (((size_t)(1 + z)*JT_ + J) << 6) + ((o ^ (J & 7)) << 3);
        bf16 th[8], tl[8];
#pragma unroll
        for (int u = 0; u < 8; u++) {
            float vv = Dt[(tq*64 + o*8 + u)*129 + w];
            bf16 hv = __float2bfloat16(vv);
            th[u] = hv;
            tl[u] = __float2bfloat16(vv - bf2f(hv));
        }
        *(uint4*)(g_hch + ob) = *(uint4*)th;
        *(uint4*)(g_hcl + ob) = *(uint4*)tl;
    }
}

// ---------------- launch ----------------
extern "C" void kernel_launch(void* const* d_in, const int* in_sizes, int n_in,
                              void* d_out, int out_size) {
    const float* x    = (const float*)d_in[0];
    const float* tem  = (const float*)d_in[1];
    float* out = (float*)d_out;

    GemmArgs base = {};
    float *p_qkvJ, *p_bqkv, *p_bo, *p_bh, *p_b3u;
    cudaGetSymbolAddress((void**)&p_qkvJ, g_qkvJ);
    cudaGetSymbolAddress((void**)&p_bqkv, g_bqkv);
    cudaGetSymbolAddress((void**)&p_bo,   g_bo);
    cudaGetSymbolAddress((void**)&p_bh,   g_bh);
    cudaGetSymbolAddress((void**)&p_b3u,  g_b3u);
    bf16 *p_xeh, *p_xel, *p_atth, *p_attl, *p_hch, *p_hcl, *p_h01h, *p_h01l;
    bf16 *p_wqkvh, *p_wqkvl, *p_woh, *p_wol, *p_wgh, *p_wgl, *p_w3h, *p_w3l;
    cudaGetSymbolAddress((void**)&p_xeh, g_xeh);   cudaGetSymbolAddress((void**)&p_xel, g_xel);
    cudaGetSymbolAddress((void**)&p_atth, g_atth); cudaGetSymbolAddress((void**)&p_attl, g_attl);
    cudaGetSymbolAddress((void**)&p_hch, g_hch);   cudaGetSymbolAddress((void**)&p_hcl, g_hcl);
    cudaGetSymbolAddress((void**)&p_h01h, g_h01h); cudaGetSymbolAddress((void**)&p_h01l, g_h01l);
    cudaGetSymbolAddress((void**)&p_wqkvh, g_wqkvh); cudaGetSymbolAddress((void**)&p_wqkvl, g_wqkvl);
    cudaGetSymbolAddress((void**)&p_woh, g_woh);   cudaGetSymbolAddress((void**)&p_wol, g_wol);
    cudaGetSymbolAddress((void**)&p_wgh, g_wgh);   cudaGetSymbolAddress((void**)&p_wgl, g_wgl);
    cudaGetSymbolAddress((void**)&p_w3h, g_w3h);   cudaGetSymbolAddress((void**)&p_w3l, g_w3l);

    const int S0 = 1024 + 2*2*24576 + 2*32768 + 36864;   // QKV: 201728
    const int S1 = 1024 + 1*2*8192  + 2*32768 + 36864;   // WO:  119808
    const int S2 = 1024 + 2*(32768 + 2*16384) + 36864;   // MODE2 streaming: 168960
    const int S3 = S0;                                   // W3
    cudaFuncSetAttribute(k_gemm<128,192,0>, cudaFuncAttributeMaxDynamicSharedMemorySize, S0);
    cudaFuncSetAttribute(k_gemm<64,64,1>,   cudaFuncAttributeMaxDynamicSharedMemorySize, S1);
    cudaFuncSetAttribute(k_gemm<320,128,2>, cudaFuncAttributeMaxDynamicSharedMemorySize, S2);
    cudaFuncSetAttribute(k_gemm<128,192,3>, cudaFuncAttributeMaxDynamicSharedMemorySize, S3);
    cudaFuncSetAttribute(k_nconv_tc,        cudaFuncAttributeMaxDynamicSharedMemorySize, NSMEM);

    k_wsplit<<<370, 256>>>(
        (const float*)d_in[8],  (const float*)d_in[9],
        (const float*)d_in[10], (const float*)d_in[11],
        (const float*)d_in[12], (const float*)d_in[13],
        (const float*)d_in[14], (const float*)d_in[15],
        (const float*)d_in[16], (const float*)d_in[17],
        (const float*)d_in[18], (const float*)d_in[19],
        (const float*)d_in[20], (const float*)d_in[21],
        (const float*)d_in[22]);
    k_split_A<<<2048, 256>>>((const float*)d_in[2], (const float*)d_in[3],
                             (const float*)d_in[4], (const float*)d_in[5]);
    k_xe<<<4096, 256>>>(x, tem, (const float*)d_in[6], (const float*)d_in[7]);

    GemmArgs a = base;
    a.ah = p_xeh; a.al = p_xel; a.wh = p_wqkvh; a.wl = p_wqkvl;
    a.bias = p_bqkv; a.outf = p_qkvJ;
    k_gemm<128,192,0><<<GB_, 256, S0>>>(a);

    k_attn<<<16384, 256>>>();

    a = base;
    a.ah = p_atth; a.al = p_attl; a.wh = p_woh; a.wl = p_wol;
    a.bias = p_bo; a.oh = p_hch; a.ol = p_hcl;
    k_gemm<64,64,1><<<GB_, 256, S1>>>(a);

    k_xt<<<dim3(16, 20, 16), 256>>>();
    k_nconv_tc<<<dim3(80, 8, 4), 256, NSMEM>>>();

    a = base;
    a.ah = p_hch; a.al = p_hcl; a.wh = p_wgh; a.wl = p_wgl;
    a.bias = p_bh; a.oh = p_h01h; a.ol = p_h01l;
    k_gemm<320,128,2><<<GB_, 256, S2>>>(a);

    a = base;
    a.ah = p_h01h; a.al = p_h01l; a.wh = p_w3h; a.wl = p_w3l;
    a.bias = p_b3u; a.outfin = out;
    k_gemm<128,192,3><<<GB_, 256, S3>>>(a);
}

// round 12
// speedup vs baseline: 1.4122x; 1.4122x over previous
#include <cuda_runtime.h>
#include <cuda_bf16.h>
#include <cstdint>

#define B_   16
#define N_   1024
#define TO_  20
#define JT_  327680
#define JPB  8
#define GB_  320

#if defined(__CUDA_ARCH_FEAT_SM103_ALL) || defined(__CUDA_ARCH_FEAT_SM100_ALL)
#define TC_PATH 1
#endif

typedef __nv_bfloat16 bf16;

// chunk-blocked pre-swizzled layouts: [kc][row][64 bf16], unit o stored at o^(row&7)
__device__ float g_qkvJ[(size_t)JT_*192];
__device__ __align__(256) bf16 g_xeh[(size_t)JT_*128], g_xel[(size_t)JT_*128];
__device__ __align__(256) bf16 g_atth[(size_t)JT_*64], g_attl[(size_t)JT_*64];
__device__ __align__(256) bf16 g_hch[(size_t)JT_*320], g_hcl[(size_t)JT_*320];
__device__ __align__(256) bf16 g_xth[(size_t)20480*1024], g_xtl[(size_t)20480*1024];
__device__ __align__(256) bf16 g_h01h[(size_t)JT_*128], g_h01l[(size_t)JT_*128];
__device__ __align__(256) bf16 g_Ah[4*1024*1024], g_Al[4*1024*1024];
__device__ __align__(256) bf16 g_wqkvh[24576], g_wqkvl[24576];
__device__ __align__(256) bf16 g_woh[4096],   g_wol[4096];
__device__ __align__(256) bf16 g_wgh[40960],  g_wgl[40960];
__device__ __align__(256) bf16 g_w3h[24576],  g_w3l[24576];
__device__ float g_bqkv[192], g_bo[64], g_bh[128], g_b3u[64];

__device__ __forceinline__ float bf2f(bf16 v) { return __bfloat162float(v); }
__device__ __forceinline__ uint32_t smem_u32(const void* p) {
    uint32_t a;
    asm("{ .reg .u64 t; cvta.to.shared.u64 t, %1; cvt.u32.u64 %0, t; }" : "=r"(a) : "l"(p));
    return a;
}
__device__ __forceinline__ int swe(int row, int k) { return ((((k >> 3) ^ (row & 7)) << 3) | (k & 7)); }

#ifdef TC_PATH
__device__ __forceinline__ uint32_t elect1() {
    uint32_t p;
    asm volatile("{\n\t.reg .pred p;\n\telect.sync _|p, 0xFFFFFFFF;\n\tselp.b32 %0, 1, 0, p;\n\t}" : "=r"(p));
    return p;
}
#define MBARRIER_INIT(addr, cnt) \
    asm volatile("mbarrier.init.shared.b64 [%0], %1;" :: "r"(addr), "r"(cnt) : "memory")
#define MBARRIER_INVAL(addr) \
    asm volatile("mbarrier.inval.shared.b64 [%0];" :: "r"(addr) : "memory")
#define MBAR_EXPECT(mbar, bytes) \
    asm volatile("mbarrier.arrive.expect_tx.shared.b64 _, [%0], %1;" \
        :: "r"((uint32_t)(mbar)), "r"((uint32_t)(bytes)) : "memory")
#define BULK_G2S(dst, src, bytes, mbar) \
    asm volatile("cp.async.bulk.shared::cluster.global.mbarrier::complete_tx::bytes [%0], [%1], %2, [%3];" \
        :: "r"((uint32_t)(dst)), "l"(src), "r"((uint32_t)(bytes)), "r"((uint32_t)(mbar)) : "memory")
#define MBAR_WAIT(mb, par) do { \
    uint32_t _m = (uint32_t)(mb), _p = (uint32_t)(par), _d; \
    asm volatile("{\n\t.reg .pred p;\n\t" \
        "mbarrier.try_wait.parity.acquire.cta.shared::cta.b64 p, [%1], %2;\n\t" \
        "selp.b32 %0, 1, 0, p;\n\t}" : "=r"(_d) : "r"(_m), "r"(_p) : "memory"); \
    if (!_d) { \
        asm volatile("{\n\t.reg .pred P1;\n\t" \
            "WL_%=:\n\t" \
            "mbarrier.try_wait.parity.acquire.cta.shared::cta.b64 P1, [%0], %1, 0x989680;\n\t" \
            "@P1 bra.uni WD_%=;\n\tbra.uni WL_%=;\n\tWD_%=:\n\t}" \
            :: "r"(_m), "r"(_p) : "memory"); \
    } \
} while(0)
#define TC_ALLOC(saddr, n) \
    asm volatile("tcgen05.alloc.cta_group::1.sync.aligned.shared::cta.b32 [%0], %1;" \
        :: "r"((uint32_t)(saddr)), "r"((uint32_t)(n)) : "memory")
#define TC_DEALLOC(tmem, n) \
    asm volatile("tcgen05.dealloc.cta_group::1.sync.aligned.b32 %0, %1;" :: "r"(tmem), "r"((uint32_t)(n)))
#define TC_RELINQ() asm volatile("tcgen05.relinquish_alloc_permit.cta_group::1.sync.aligned;")
#define TC_COMMIT(mbar) \
    asm volatile("tcgen05.commit.cta_group::1.mbarrier::arrive::one.shared::cluster.b64 [%0];" \
        :: "r"((uint32_t)(mbar)) : "memory")
#define TC_FENCE_AFTER() asm volatile("tcgen05.fence::after_thread_sync;" ::: "memory")
#define TC_WAIT_LD() asm volatile("tcgen05.wait::ld.sync.aligned;" ::: "memory")
#define TC_LD_X32(r, ta) \
    asm volatile("tcgen05.ld.sync.aligned.32x32b.x32.b32 " \
        "{%0, %1, %2, %3, %4, %5, %6, %7, %8, %9, %10, %11, %12, %13, %14, %15, " \
        " %16, %17, %18, %19, %20, %21, %22, %23, %24, %25, %26, %27, %28, %29, %30, %31}, [%32];" \
        : "=r"((r)[0]),  "=r"((r)[1]),  "=r"((r)[2]),  "=r"((r)[3]), \
          "=r"((r)[4]),  "=r"((r)[5]),  "=r"((r)[6]),  "=r"((r)[7]), \
          "=r"((r)[8]),  "=r"((r)[9]),  "=r"((r)[10]), "=r"((r)[11]), \
          "=r"((r)[12]), "=r"((r)[13]), "=r"((r)[14]), "=r"((r)[15]), \
          "=r"((r)[16]), "=r"((r)[17]), "=r"((r)[18]), "=r"((r)[19]), \
          "=r"((r)[20]), "=r"((r)[21]), "=r"((r)[22]), "=r"((r)[23]), \
          "=r"((r)[24]), "=r"((r)[25]), "=r"((r)[26]), "=r"((r)[27]), \
          "=r"((r)[28]), "=r"((r)[29]), "=r"((r)[30]), "=r"((r)[31]) \
        : "r"(ta))
__device__ __forceinline__ uint64_t make_desc(uint32_t addr) {
    return 0x4000404000010000ULL | (uint64_t)((addr >> 4) & 0x3FFF);
}
__device__ __forceinline__ void mma_bf(uint32_t d, uint64_t a, uint64_t b, uint32_t idesc, bool acc) {
    uint32_t en = acc ? 1u : 0u;
    asm volatile("{\n\t.reg .pred p;\n\tsetp.ne.u32 p, %5, 0;\n\t"
        "tcgen05.mma.cta_group::1.kind::f16 [%0], %1, %2, %3, {%4, %4, %4, %4}, p;\n\t}"
        :: "r"(d), "l"(a), "l"(b), "r"(idesc), "r"(0u), "r"(en) : "memory");
}
#define IDESC(n) (0x8000490u | (((n)/8) << 17))
#endif

// ---------------- weight split/pack (pre-swizzled) ----------------
__global__ void k_wsplit(const float* __restrict__ wq, const float* __restrict__ bq,
                         const float* __restrict__ wk, const float* __restrict__ bk,
                         const float* __restrict__ wv, const float* __restrict__ bv,
                         const float* __restrict__ wo, const float* __restrict__ bo,
                         const float* __restrict__ wg0, const float* __restrict__ bg0,
                         const float* __restrict__ wg1, const float* __restrict__ bg1,
                         const float* __restrict__ wadp, const float* __restrict__ badp,
                         const float* __restrict__ w0f) {
    int i = blockIdx.x * 256 + threadIdx.x;
    if (i < 24576) {
        int c = i / 12288, rem = i % 12288, r = rem / 64, k = rem & 63, col = c*64 + k;
        int s = r / 64, rr = r % 64;
        const float* W = (s == 0) ? wq : (s == 1) ? wk : wv;
        float v = (col < 96) ? W[rr*96 + col] : 0.f;
        bf16 h = __float2bfloat16(v);
        int si = (c*192 + r)*64 + swe(r, k);
        g_wqkvh[si] = h; g_wqkvl[si] = __float2bfloat16(v - bf2f(h));
    } else if (i < 28672) {
        int j = i - 24576;
        int n = j >> 6, k = j & 63;
        float v = wo[j];
        bf16 h = __float2bfloat16(v);
        int si = (n << 6) + swe(n, k);
        g_woh[si] = h; g_wol[si] = __float2bfloat16(v - bf2f(h));
    } else if (i < 69632) {
        int j = i - 28672;
        int c = j / 8192, rem = j % 8192, r = rem / 64, k = rem & 63, col = c*64 + k;
        float v;
        if (r < 64) v = (col < 192) ? wg0[r*192 + col] : 0.f;
        else {
            int rr = r - 64;
            if (col < 64) v = wg1[rr*192 + col];
            else if (col >= 192) v = wg1[rr*192 + col - 128];
            else v = 0.f;
        }
        bf16 h = __float2bfloat16(v);
        int si = (c*128 + r)*64 + swe(r, k);
        g_wgh[si] = h; g_wgl[si] = __float2bfloat16(v - bf2f(h));
    } else if (i < 94208) {
        int j = i - 69632;
        int c = j / 12288, rem = j % 12288, r = rem / 64, k = rem & 63, col = c*64 + k;
        float v;
        if (r < 64)       v = wadp[r*128 + col];
        else if (r < 128) v = (col < 64) ? w0f[(r-64)*64 + col] : 0.f;
        else              v = (col >= 64) ? w0f[(r-128)*64 + col - 64] : 0.f;
        bf16 h = __float2bfloat16(v);
        int si = (c*192 + r)*64 + swe(r, k);
        g_w3h[si] = h; g_w3l[si] = __float2bfloat16(v - bf2f(h));
    } else if (i < 94656) {
        int j = i - 94208;
        if (j < 192)      g_bqkv[j] = (j < 64) ? bq[j] : (j < 128) ? bk[j-64] : bv[j-128];
        else if (j < 256) g_bo[j-192] = bo[j-192];
        else if (j < 384) { int j2 = j-256; g_bh[j2] = (j2 < 64) ? bg0[j2] : bg1[j2-64]; }
        else              g_b3u[j-384] = badp[j-384];
    }
}

// ---------------- split graph matrices ----------------
__global__ void k_split_A(const float* __restrict__ A0, const float* __restrict__ A1,
                          const float* __restrict__ A2, const float* __restrict__ A3) {
    int u = blockIdx.x * 256 + threadIdx.x;
    int z = u >> 17, rem = u & 131071;
    int m = rem >> 7, uo = rem & 127;
    int kc = uo >> 3, o = uo & 7;
    const float* A = (z == 0) ? A0 : (z == 1) ? A1 : (z == 2) ? A2 : A3;
    const float* src = A + (size_t)m*1024 + uo*8;
    bf16 th[8], tl[8];
#pragma unroll
    for (int e = 0; e < 8; e++) {
        float v = src[e];
        bf16 h = __float2bfloat16(v);
        th[e] = h; tl[e] = __float2bfloat16(v - bf2f(h));
    }
    size_t dst = (((size_t)(z*16 + kc)*1024 + m) << 6) + ((o ^ (m & 7)) << 3);
    *(uint4*)(g_Ah + dst) = *(uint4*)th;
    *(uint4*)(g_Al + dst) = *(uint4*)tl;
}

// ---------------- fused dilated conv + tem slice -> xe ----------------
__global__ __launch_bounds__(256) void k_xe(const float* __restrict__ x,
                                            const float* __restrict__ tem,
                                            const float* __restrict__ w,
                                            const float* __restrict__ bias) {
    __shared__ float pool[9376];
    float* xs = pool;
    float* ws = pool + 3072;
    float* bs = pool + 9312;
    int tid = threadIdx.x;
    int b = blockIdx.x >> 8, n0 = (blockIdx.x & 255) * 4;
    for (int i = tid; i < 64*96; i += 256) { int o = i / 96, kk = i % 96; ws[kk*65 + o] = w[i]; }
    if (tid < 64) bs[tid] = bias[tid];
    for (int i = tid; i < 3072; i += 256) {
        int nn = i / 768, r = i % 768, ci = r / 24, tt = r % 24;
        xs[(nn*32 + ci)*24 + tt] = x[((size_t)(b*32 + ci)*1024 + n0 + nn)*24 + tt];
    }
    __syncthreads();
    int co = tid & 63, nn = tid >> 6;
    float acc[20];
#pragma unroll
    for (int t = 0; t < 20; t++) acc[t] = bs[co];
    for (int ci = 0; ci < 32; ci++) {
        float w0 = ws[(ci*3+0)*65 + co], w1 = ws[(ci*3+1)*65 + co], w2 = ws[(ci*3+2)*65 + co];
        const float* xr = &xs[(nn*32 + ci)*24];
#pragma unroll
        for (int t = 0; t < 20; t++) acc[t] += w0*xr[t] + w1*xr[t+2] + w2*xr[t+4];
    }
    __syncthreads();
    float* sxe = pool;
#pragma unroll
    for (int t = 0; t < 20; t++) sxe[(nn*20 + t)*96 + co] = fmaxf(acc[t], 0.f);
    for (int i = tid; i < 2560; i += 256) {
        int nn2 = i / 640, r = i % 640, ci = r / 20, t = r % 20;
        sxe[(nn2*20 + t)*96 + 64 + ci] = tem[((size_t)(b*32 + ci)*1024 + n0 + nn2)*24 + 4 + t];
    }
    __syncthreads();
    for (int idx = tid; idx < 2560; idx += 256) {
        int half = idx >= 1280;
        int e = half ? idx - 1280 : idx;
        int rr = e >> 4, uo = e & 15;
        int kc = uo >> 3, o = uo & 7;
        int nn2 = rr / 20, t = rr % 20;
        size_t J = (size_t)((b*1024 + n0 + nn2)*20 + t);
        const float* srow = &sxe[rr*96];
        bf16 tmp[8];
#pragma unroll
        for (int u = 0; u < 8; u++) {
            int c = uo*8 + u;
            float vv = (c < 96) ? srow[c] : 0.f;
            bf16 hv = __float2bfloat16(vv);
            tmp[u] = half ? __float2bfloat16(vv - bf2f(hv)) : hv;
        }
        size_t dst = (((size_t)kc*JT_ + J) << 6) + ((o ^ (J & 7)) << 3);
        *(uint4*)((half ? g_xel : g_xeh) + dst) = *(uint4*)tmp;
    }
}

// ---------------- persistent multi-tile tensor-core GEMM (depth-3 pipeline) ----------------
struct GemmArgs {
    const bf16 *ah, *al;      // [K/64][JT][64] pre-swizzled
    const bf16 *wh, *wl;      // [K/64][N][64] pre-swizzled
    const float* bias;
    float* outf;              // MODE 0
    bf16 *oh, *ol;            // MODE 1/2: [Nout/64][JT][64]
    float* outfin;            // MODE 3
};

template<int K_, int NN, int MODE>
__global__ __launch_bounds__(256) void k_gemm(GemmArgs p) {
    constexpr int NCH = K_ / 64;
    constexpr int WB  = NN * 128;
    constexpr bool WRES = (K_ <= 128);
    constexpr int WRB  = WRES ? NCH*2*WB : 0;
    constexpr int ASTG = WRES ? 32768 : 32768 + 2*WB;
    constexpr int GT  = JPB * NCH;
    extern __shared__ char smem[];
    int tid = threadIdx.x, wid = tid >> 5, lane = tid & 31;
    size_t J0 = (size_t)blockIdx.x * (JPB*128);
    float* Dt = (float*)(smem + 1024 + WRB + 3*ASTG);   // MODE0/1/2: [64][68]; MODE3: [64][132]

#ifdef TC_PATH
    uint32_t sb = smem_u32(smem);
    if (wid == 0) TC_ALLOC(sb, 512);
    if (tid == 0) {
        MBARRIER_INIT(sb+8, 1);  MBARRIER_INIT(sb+16, 1); MBARRIER_INIT(sb+24, 1);  // full[0..2]
        MBARRIER_INIT(sb+32, 1); MBARRIER_INIT(sb+40, 1); MBARRIER_INIT(sb+48, 1);  // mma[0..2]
        MBARRIER_INIT(sb+56, 1);                                                     // weights
    }
    __syncthreads();
    uint32_t tmem;
    asm volatile("ld.shared.b32 %0, [%1];" : "=r"(tmem) : "r"(sb));
    uint32_t wbase = sb + 1024;
    uint32_t abase = sb + 1024 + WRB;

    auto load_stage = [&](int g) {
        int tile = g / NCH, c = g % NCH;
        uint32_t st = abase + (g % 3)*ASTG;
        uint32_t mb = sb + 8 + 8*(g % 3);
        MBAR_EXPECT(mb, ASTG);
        const bf16* as = p.ah + (((size_t)c*JT_ + J0 + tile*128) << 6);
        const bf16* ls = p.al + (((size_t)c*JT_ + J0 + tile*128) << 6);
        BULK_G2S(st,         as, 16384, mb);
        BULK_G2S(st + 16384, ls, 16384, mb);
        if (!WRES) {
            BULK_G2S(st + 32768,      p.wh + ((size_t)c*NN << 6), WB, mb);
            BULK_G2S(st + 32768 + WB, p.wl + ((size_t)c*NN << 6), WB, mb);
        }
    };

    int pending = -1;
    int sub = wid & 3, grp = wid >> 2;
    int m = sub*32 + lane;

    auto epilogue = [&](int tile) {
        TC_FENCE_AFTER();
        size_t J0t = J0 + (size_t)tile*128;
        uint32_t ta = tmem + (tile & 1)*256;
        if (MODE != 3) {
            for (int rh = 0; rh < 2; rh++) {
#pragma unroll
                for (int pp = 0; pp < NN/64; pp++) {
                    if (wid < 4 && (wid >> 1) == rh) {
                        uint32_t r[64];
                        TC_LD_X32(r,      ta + pp*64);
                        TC_LD_X32(r + 32, ta + pp*64 + 32);
                        TC_WAIT_LD();
                        int lr = (wid & 1)*32 + lane;
#pragma unroll
                        for (int c = 0; c < 64; c++) Dt[lr*68 + c] = __uint_as_float(r[c]);
                    }
                    __syncthreads();
                    if (MODE == 0) {
                        for (int idx = tid; idx < 1024; idx += 256) {
                            int rr = idx >> 4, o = idx & 15;
                            float4 v;
                            v.x = Dt[rr*68 + o*4 + 0] + p.bias[pp*64 + o*4 + 0];
                            v.y = Dt[rr*68 + o*4 + 1] + p.bias[pp*64 + o*4 + 1];
                            v.z = Dt[rr*68 + o*4 + 2] + p.bias[pp*64 + o*4 + 2];
                            v.w = Dt[rr*68 + o*4 + 3] + p.bias[pp*64 + o*4 + 3];
                            *(float4*)(p.outf + (J0t + rh*64 + rr)*192 + pp*64 + o*4) = v;
                        }
                    } else {
                        for (int idx = tid; idx < 512; idx += 256) {
                            int rr = idx >> 3, o = idx & 7;
                            size_t J = J0t + rh*64 + rr;
                            bf16 th[8], tl[8];
#pragma unroll
                            for (int u = 0; u < 8; u++) {
                                float v = fmaxf(Dt[rr*68 + o*8 + u] + p.bias[pp*64 + o*8 + u], 0.f);
                                bf16 hv = __float2bfloat16(v);
                                th[u] = hv;
                                tl[u] = __float2bfloat16(v - bf2f(hv));
                            }
                            size_t ob = (((size_t)pp*JT_ + J) << 6) + ((o ^ (J & 7)) << 3);
                            *(uint4*)(p.oh + ob) = *(uint4*)th;
                            *(uint4*)(p.ol + ob) = *(uint4*)tl;
                        }
                    }
                    __syncthreads();
                }
            }
        } else {
            float* sfin = Dt;                        // [64][132]
            uint32_t r[128];
            if (grp == 0) {
                TC_LD_X32(r,      ta);
                TC_LD_X32(r + 32, ta + 32);
                TC_LD_X32(r + 64, ta + 64);
                TC_LD_X32(r + 96, ta + 96);
            } else {
                TC_LD_X32(r,      ta + 128);
                TC_LD_X32(r + 32, ta + 160);
            }
            TC_WAIT_LD();
            if (grp == 1)
                for (int c = 0; c < 64; c++) sfin[c*132 + m] = __uint_as_float(r[c]);
            __syncthreads();
            if (grp == 0) {
                float s0 = 0.f, s1 = 0.f;
#pragma unroll
                for (int c = 0; c < 64; c++) {
                    float u = __uint_as_float(r[c]) + p.bias[c];
                    s0 += u * __uint_as_float(r[64 + c]);
                    s1 += u * sfin[c*132 + m];
                }
                float mx = fmaxf(s0, s1);
                float e0 = __expf(s0 - mx), e1 = __expf(s1 - mx);
                float inv = 1.f / (e0 + e1);
                float a0 = e0*inv, a1 = e1*inv;
                for (int c = 0; c < 64; c++)
                    sfin[c*132 + m] = a0*__uint_as_float(r[64 + c]) + a1*sfin[c*132 + m];
            }
            __syncthreads();
            int b = (int)(J0t / 20480);
            int joff = (int)(J0t % 20480);
            for (int idx = tid; idx < 2048; idx += 256) {
                int c = idx >> 5, o = idx & 31;
                float4 v;
                v.x = sfin[c*132 + o*4 + 0];
                v.y = sfin[c*132 + o*4 + 1];
                v.z = sfin[c*132 + o*4 + 2];
                v.w = sfin[c*132 + o*4 + 3];
                *(float4*)(p.outfin + (size_t)(b*64 + c)*20480 + joff + o*4) = v;
            }
            __syncthreads();
        }
    };

    if (wid == 0) {
        if (elect1()) {
            if (WRES) {
                MBAR_EXPECT(sb+56, WRB);
                for (int c = 0; c < NCH; c++) {
                    BULK_G2S(wbase + (c*2)*WB,   p.wh + ((size_t)c*NN << 6), WB, sb+56);
                    BULK_G2S(wbase + (c*2+1)*WB, p.wl + ((size_t)c*NN << 6), WB, sb+56);
                }
            }
            load_stage(0);
            if (GT > 1) load_stage(1);
        }
    }
    for (int g = 0; g < GT; g++) {
        // all threads track mma phases sequentially (buffer reuse + epilogue guard)
        if (g >= 1) MBAR_WAIT(sb + 32 + 8*((g - 1) % 3), ((g - 1) / 3) & 1);
        if (wid == 0) {
            if (elect1()) {
                if (g + 2 < GT) load_stage(g + 2);
                if (WRES && g == 0) MBAR_WAIT(sb+56, 0);
                MBAR_WAIT(sb + 8 + 8*(g % 3), (g / 3) & 1);
                int c = g % NCH, tile = g / NCH;
                uint32_t s0 = abase + (g % 3)*ASTG;
                uint64_t ah = make_desc(s0);
                uint64_t al = make_desc(s0 + 16384);
                uint64_t wh = WRES ? make_desc(wbase + (c*2)*WB)   : make_desc(s0 + 32768);
                uint64_t wl = WRES ? make_desc(wbase + (c*2+1)*WB) : make_desc(s0 + 32768 + WB);
                uint32_t d = tmem + (tile & 1)*256;
#pragma unroll
                for (int ks = 0; ks < 4; ks++) {
                    mma_bf(d, ah + 2*ks, wh + 2*ks, IDESC(NN), !(c == 0 && ks == 0));
                    mma_bf(d, ah + 2*ks, wl + 2*ks, IDESC(NN), true);
                    mma_bf(d, al + 2*ks, wh + 2*ks, IDESC(NN), true);
                }
                TC_COMMIT(sb + 32 + 8*(g % 3));
            }
        }
        if (pending >= 0) { epilogue(pending); pending = -1; }
        if (g % NCH == NCH - 1) pending = g / NCH;
    }
    MBAR_WAIT(sb + 32 + 8*((GT - 1) % 3), ((GT - 1) / 3) & 1);
    epilogue(pending);
    __syncthreads();
    if (tid == 0) {
        MBARRIER_INVAL(sb+8);  MBARRIER_INVAL(sb+16); MBARRIER_INVAL(sb+24);
        MBARRIER_INVAL(sb+32); MBARRIER_INVAL(sb+40); MBARRIER_INVAL(sb+48);
        MBARRIER_INVAL(sb+56);
    }
    if (wid == 0) { TC_RELINQ(); TC_DEALLOC(tmem, 512); }
#else
    for (int tile = 0; tile < JPB; tile++) {
        for (int mm = tid; mm < 128; mm += 256) {
            size_t J = J0 + (size_t)tile*128 + mm;
            float res[MODE == 3 ? 192 : NN];
            for (int n = 0; n < (MODE == 3 ? 192 : NN); n++) {
                float acc = 0.f;
                for (int k = 0; k < K_; k++) {
                    size_t ai = (((size_t)(k >> 6)*JT_ + J) << 6) + swe((int)(J & 7), k & 63);
                    float av = bf2f(p.ah[ai]) + bf2f(p.al[ai]);
                    size_t wi = (((size_t)(k >> 6)*NN + n) << 6) + swe(n, k & 63);
                    acc += av * (bf2f(p.wh[wi]) + bf2f(p.wl[wi]));
                }
                res[n] = acc;
            }
            if (MODE == 0) {
                for (int n = 0; n < NN; n++) p.outf[J*192 + n] = res[n] + p.bias[n];
            } else if (MODE == 3) {
                float s0 = 0.f, s1 = 0.f;
                for (int c = 0; c < 64; c++) {
                    float u = res[c] + p.bias[c];
                    s0 += u*res[64+c]; s1 += u*res[128+c];
                }
                float mx = fmaxf(s0, s1);
                float e0 = __expf(s0-mx), e1 = __expf(s1-mx), inv = 1.f/(e0+e1);
                int b = (int)(J/20480), rr = (int)(J%20480);
                for (int c = 0; c < 64; c++)
                    p.outfin[(size_t)(b*64+c)*20480 + rr] = (e0*res[64+c]+e1*res[128+c])*inv;
            } else {
                for (int n = 0; n < NN; n++) {
                    float v = fmaxf(res[n] + p.bias[n], 0.f);
                    bf16 hv = __float2bfloat16(v);
                    size_t ob = (((size_t)(n >> 6)*JT_ + J) << 6) + swe((int)(J & 7), n & 63);
                    p.oh[ob] = hv;
                    p.ol[ob] = __float2bfloat16(v - bf2f(hv));
                }
            }
        }
    }
#endif
}

// ---------------- attention: block per (b,n), warp per head ----------------
__global__ __launch_bounds__(256) void k_attn() {
    __shared__ float sq[20*196];
    __shared__ float Ss[8][400];
    __shared__ bf16 soh[20*72], sol[20*72];
    int tid = threadIdx.x, wid = tid >> 5, lane = tid & 31;
    size_t Jb = (size_t)blockIdx.x * 20;

    for (int idx = tid; idx < 960; idx += 256) {
        int t = idx / 48, o = idx % 48;
        *(float4*)&sq[t*196 + o*4] = *(const float4*)(g_qkvJ + (Jb + t)*192 + o*4);
    }
    __syncthreads();
    int h = wid;
    float* S = Ss[h];
    const int hb = h*8;
    for (int idx = lane; idx < 400; idx += 32) {
        int t = idx / 20, s = idx % 20;
        if (s <= t) {
            float acc = 0.f;
#pragma unroll
            for (int d = 0; d < 8; d++) acc += sq[t*196 + hb + d] * sq[s*196 + 64 + hb + d];
            S[idx] = acc * 0.35355339059327373f;
        }
    }
    __syncwarp();
    if (lane < 20) {
        int t = lane;
        float mx = -1e30f;
        for (int s = 0; s <= t; s++) mx = fmaxf(mx, S[t*20 + s]);
        float sum = 0.f;
        for (int s = 0; s <= t; s++) { float e = __expf(S[t*20 + s] - mx); S[t*20 + s] = e; sum += e; }
        float inv = 1.f / sum;
        for (int s = 0; s <= t; s++) S[t*20 + s] *= inv;
    }
    __syncwarp();
    for (int idx = lane; idx < 160; idx += 32) {
        int d = idx / 20, t = idx % 20;
        float acc = 0.f;
        for (int s = 0; s <= t; s++) acc += S[t*20 + s] * sq[s*196 + 128 + hb + d];
        bf16 hv = __float2bfloat16(acc);
        soh[t*72 + hb + d] = hv;
        sol[t*72 + hb + d] = __float2bfloat16(acc - bf2f(hv));
    }
    __syncthreads();
    if (tid < 160) {
        int t = tid >> 3, o = tid & 7;
        size_t J = Jb + t;
        size_t ob = (J << 6) + ((o ^ (J & 7)) << 3);
        bf16 th[8], tl[8];
#pragma unroll
        for (int u = 0; u < 8; u++) { th[u] = soh[t*72 + o*8 + u]; tl[u] = sol[t*72 + o*8 + u]; }
        *(uint4*)(g_atth + ob) = *(uint4*)th;
        *(uint4*)(g_attl + ob) = *(uint4*)tl;
    }
}

// ---------------- transpose x2 (hc kc=0) -> xt[kc][(b,t,c)][64] pre-swizzled ----------------
__global__ __launch_bounds__(256) void k_xt() {
    __shared__ bf16 th[64][72], tl[64][72];
    int tid = threadIdx.x;
    int b = blockIdx.x, t = blockIdx.y, n0 = blockIdx.z * 64;
    for (int i = tid; i < 512; i += 256) {
        int r = i >> 3, o = i & 7;
        size_t J = ((size_t)(b*1024 + n0 + r)*20 + t);
        size_t src = (J << 6) + ((o ^ (J & 7)) << 3);
        *(uint4*)(&th[r][o*8]) = *(const uint4*)(g_hch + src);
        *(uint4*)(&tl[r][o*8]) = *(const uint4*)(g_hcl + src);
    }
    __syncthreads();
    for (int i = tid; i < 512; i += 256) {
        int c = i >> 3, n8 = i & 7;
        bf16 vh[8], vl[8];
#pragma unroll
        for (int u = 0; u < 8; u++) { vh[u] = th[n8*8 + u][c]; vl[u] = tl[n8*8 + u][c]; }
        int j = b*1280 + t*64 + c;
        size_t dst = (((size_t)blockIdx.z*20480 + j) << 6) + ((n8 ^ (j & 7)) << 3);
        *(uint4*)(g_xth + dst) = *(uint4*)vh;
        *(uint4*)(g_xtl + dst) = *(uint4*)vl;
    }
}

// ---------------- nconv (bulk-copy pipeline, unchanged R9) ----------------
#define NSTG 98304
#define NSMEM (1024 + 2*NSTG)
__global__ __launch_bounds__(256) void k_nconv_tc() {
    extern __shared__ char smem[];
    int tid = threadIdx.x, wid = tid >> 5, lane = tid & 31;
    int j0 = blockIdx.x * 256, m0 = blockIdx.y * 128, z = blockIdx.z;
    float* Dt = (float*)(smem + 1024);

#ifdef TC_PATH
    uint32_t sb = smem_u32(smem);
    if (wid == 0) TC_ALLOC(sb, 256);
    if (tid == 0) {
        MBARRIER_INIT(sb+8, 1);  MBARRIER_INIT(sb+16, 1);
        MBARRIER_INIT(sb+24, 1); MBARRIER_INIT(sb+32, 1);
    }
    __syncthreads();
    uint32_t tmem;
    asm volatile("ld.shared.b32 %0, [%1];" : "=r"(tmem) : "r"(sb));
    uint32_t bufb = sb + 1024;

    auto load_stage = [&](int kc, uint32_t st) {
        uint32_t mb = sb + 8 + 8*(kc & 1);
        MBAR_EXPECT(mb, NSTG);
        BULK_G2S(st,         g_Ah + (((size_t)(z*16 + kc)*1024 + m0) << 6), 16384, mb);
        BULK_G2S(st + 16384, g_Al + (((size_t)(z*16 + kc)*1024 + m0) << 6), 16384, mb);
        BULK_G2S(st + 32768, g_xth + (((size_t)kc*20480 + j0) << 6), 32768, mb);
        BULK_G2S(st + 65536, g_xtl + (((size_t)kc*20480 + j0) << 6), 32768, mb);
    };

    if (wid == 0) { if (elect1()) { load_stage(0, bufb); } }
    for (int ch = 0; ch < 16; ch++) {
        int buf = ch & 1;
        if (ch >= 1) MBAR_WAIT(sb + 24 + 8*((ch - 1) & 1), ((ch - 1) >> 1) & 1);
        if (wid == 0) {
            if (elect1()) {
                if (ch + 1 < 16) load_stage(ch + 1, bufb + (1 - buf)*NSTG);
                MBAR_WAIT(sb + 8 + 8*buf, (ch >> 1) & 1);
                uint32_t s0 = bufb + buf*NSTG;
                uint64_t ah = make_desc(s0);
                uint64_t al = make_desc(s0 + 16384);
                uint64_t xh = make_desc(s0 + 32768);
                uint64_t xl = make_desc(s0 + 65536);
#pragma unroll
                for (int ks = 0; ks < 4; ks++) {
                    mma_bf(tmem, ah + 2*ks, xh + 2*ks, IDESC(256), !(ch == 0 && ks == 0));
                    mma_bf(tmem, ah + 2*ks, xl + 2*ks, IDESC(256), true);
                    mma_bf(tmem, al + 2*ks, xh + 2*ks, IDESC(256), true);
                }
                TC_COMMIT(sb + 24 + 8*buf);
            }
        }
    }
    MBAR_WAIT(sb + 24 + 8, 1);
    TC_FENCE_AFTER();
    __syncthreads();
    {
        int sub = wid & 3, hf = wid >> 2;
        int m = sub*32 + lane;
#pragma unroll
        for (int i = 0; i < 4; i++) {
            uint32_t r[32];
            int cb = hf*128 + i*32;
            TC_LD_X32(r, tmem + cb);
            TC_WAIT_LD();
#pragma unroll
            for (int c = 0; c < 32; c++) Dt[(cb + c)*129 + m] = __uint_as_float(r[c]);
        }
    }
    __syncthreads();
    if (tid == 0) { MBARRIER_INVAL(sb+8); MBARRIER_INVAL(sb+16); MBARRIER_INVAL(sb+24); MBARRIER_INVAL(sb+32); }
    if (wid == 0) { TC_RELINQ(); TC_DEALLOC(tmem, 256); }
    __syncthreads();
#else
    for (int idx = tid; idx < 128*256; idx += 256) {
        int mm = idx >> 8, jl = idx & 255;
        int gm = m0 + mm, gj = j0 + jl;
        float acc = 0.f;
        for (int k = 0; k < 1024; k++) {
            size_t ai = (((size_t)(z*16 + (k >> 6))*1024 + gm) << 6) + swe(gm & 7, k & 63);
            size_t xi = (((size_t)(k >> 6)*20480 + gj) << 6) + swe(gj & 7, k & 63);
            acc += (bf2f(g_Ah[ai]) + bf2f(g_Al[ai])) * (bf2f(g_xth[xi]) + bf2f(g_xtl[xi]));
        }
        Dt[jl*129 + mm] = acc;
    }
    __syncthreads();
#endif

    int b = j0 / 1280, t0 = (j0 % 1280) / 64;
    for (int idx = tid; idx < 4096; idx += 256) {
        int rn = idx >> 3, o = idx & 7;
        int w = rn >> 2, tq = rn & 3;
        size_t J = (size_t)(b*1024 + m0 + w)*20 + t0 + tq;
        size_t ob = (((size_t)(1 + z)*JT_ + J) << 6) + ((o ^ (J & 7)) << 3);
        bf16 th[8], tl[8];
#pragma unroll
        for (int u = 0; u < 8; u++) {
            float vv = Dt[(tq*64 + o*8 + u)*129 + w];
            bf16 hv = __float2bfloat16(vv);
            th[u] = hv;
            tl[u] = __float2bfloat16(vv - bf2f(hv));
        }
        *(uint4*)(g_hch + ob) = *(uint4*)th;
        *(uint4*)(g_hcl + ob) = *(uint4*)tl;
    }
}

// ---------------- launch ----------------
extern "C" void kernel_launch(void* const* d_in, const int* in_sizes, int n_in,
                              void* d_out, int out_size) {
    const float* x    = (const float*)d_in[0];
    const float* tem  = (const float*)d_in[1];
    float* out = (float*)d_out;

    GemmArgs base = {};
    float *p_qkvJ, *p_bqkv, *p_bo, *p_bh, *p_b3u;
    cudaGetSymbolAddress((void**)&p_qkvJ, g_qkvJ);
    cudaGetSymbolAddress((void**)&p_bqkv, g_bqkv);
    cudaGetSymbolAddress((void**)&p_bo,   g_bo);
    cudaGetSymbolAddress((void**)&p_bh,   g_bh);
    cudaGetSymbolAddress((void**)&p_b3u,  g_b3u);
    bf16 *p_xeh, *p_xel, *p_atth, *p_attl, *p_hch, *p_hcl, *p_h01h, *p_h01l;
    bf16 *p_wqkvh, *p_wqkvl, *p_woh, *p_wol, *p_wgh, *p_wgl, *p_w3h, *p_w3l;
    cudaGetSymbolAddress((void**)&p_xeh, g_xeh);   cudaGetSymbolAddress((void**)&p_xel, g_xel);
    cudaGetSymbolAddress((void**)&p_atth, g_atth); cudaGetSymbolAddress((void**)&p_attl, g_attl);
    cudaGetSymbolAddress((void**)&p_hch, g_hch);   cudaGetSymbolAddress((void**)&p_hcl, g_hcl);
    cudaGetSymbolAddress((void**)&p_h01h, g_h01h); cudaGetSymbolAddress((void**)&p_h01l, g_h01l);
    cudaGetSymbolAddress((void**)&p_wqkvh, g_wqkvh); cudaGetSymbolAddress((void**)&p_wqkvl, g_wqkvl);
    cudaGetSymbolAddress((void**)&p_woh, g_woh);   cudaGetSymbolAddress((void**)&p_wol, g_wol);
    cudaGetSymbolAddress((void**)&p_wgh, g_wgh);   cudaGetSymbolAddress((void**)&p_wgl, g_wgl);
    cudaGetSymbolAddress((void**)&p_w3h, g_w3h);   cudaGetSymbolAddress((void**)&p_w3l, g_w3l);

    // smem budgets: 1024 + WRB + 3*ASTG + Dt
    const int S0 = 1024 + 98304 + 3*32768 + 17408;   // 215040 (QKV: WRES, Dt[64][68])
    const int S1 = 1024 + 16384 + 3*32768 + 17408;   // 133120 (WO)
    const int S2 = 1024 + 0     + 3*65536 + 17408;   // 215040 (h0|h1 streamed)
    const int S3 = 1024 + 98304 + 3*32768 + 33792;   // 231424 (W3: sfin[64][132])
    cudaFuncSetAttribute(k_gemm<128,192,0>, cudaFuncAttributeMaxDynamicSharedMemorySize, S0);
    cudaFuncSetAttribute(k_gemm<64,64,1>,   cudaFuncAttributeMaxDynamicSharedMemorySize, S1);
    cudaFuncSetAttribute(k_gemm<320,128,2>, cudaFuncAttributeMaxDynamicSharedMemorySize, S2);
    cudaFuncSetAttribute(k_gemm<128,192,3>, cudaFuncAttributeMaxDynamicSharedMemorySize, S3);
    cudaFuncSetAttribute(k_nconv_tc,        cudaFuncAttributeMaxDynamicSharedMemorySize, NSMEM);

    k_wsplit<<<370, 256>>>(
        (const float*)d_in[8],  (const float*)d_in[9],
        (const float*)d_in[10], (const float*)d_in[11],
        (const float*)d_in[12], (const float*)d_in[13],
        (const float*)d_in[14], (const float*)d_in[15],
        (const float*)d_in[16], (const float*)d_in[17],
        (const float*)d_in[18], (const float*)d_in[19],
        (const float*)d_in[20], (const float*)d_in[21],
        (const float*)d_in[22]);
    k_split_A<<<2048, 256>>>((const float*)d_in[2], (const float*)d_in[3],
                             (const float*)d_in[4], (const float*)d_in[5]);
    k_xe<<<4096, 256>>>(x, tem, (const float*)d_in[6], (const float*)d_in[7]);

    GemmArgs a = base;
    a.ah = p_xeh; a.al = p_xel; a.wh = p_wqkvh; a.wl = p_wqkvl;
    a.bias = p_bqkv; a.outf = p_qkvJ;
    k_gemm<128,192,0><<<GB_, 256, S0>>>(a);

    k_attn<<<16384, 256>>>();

    a = base;
    a.ah = p_atth; a.al = p_attl; a.wh = p_woh; a.wl = p_wol;
    a.bias = p_bo; a.oh = p_hch; a.ol = p_hcl;
    k_gemm<64,64,1><<<GB_, 256, S1>>>(a);

    k_xt<<<dim3(16, 20, 16), 256>>>();
    k_nconv_tc<<<dim3(80, 8, 4), 256, NSMEM>>>();

    a = base;
    a.ah = p_hch; a.al = p_hcl; a.wh = p_wgh; a.wl = p_wgl;
    a.bias = p_bh; a.oh = p_h01h; a.ol = p_h01l;
    k_gemm<320,128,2><<<GB_, 256, S2>>>(a);

    a = base;
    a.ah = p_h01h; a.al = p_h01l; a.wh = p_w3h; a.wl = p_w3l;
    a.bias = p_b3u; a.outfin = out;
    k_gemm<128,192,3><<<GB_, 256, S3>>>(a);
}